// round 1
// baseline (speedup 1.0000x reference)
#include <cuda_runtime.h>
#include <cstddef>
#include <cstdint>

// Problem constants (fixed by the dataset)
#define N_A   100000
#define N_P   150000
#define N_TOT (N_A + N_P)
#define D     128
#define C_OUT 16

// -------------------- device scratch (no allocs allowed) --------------------
__device__ float g_x  [(size_t)N_TOT * D];  // x after proj/relu/norm, later res2
__device__ float g_res[(size_t)N_TOT * D];  // res1
__device__ float g_hA [(size_t)N_A  * D];   // AP-SpMM output (rows in [0,N_A))
__device__ float g_hP [(size_t)N_P  * D];   // PA-SpMM output (rows in [N_A,N))
__device__ float g_W0c[D * D];              // Wp0 @ W1
__device__ float g_W1c[D * D];              // Wp1 @ W1

// -------------------- tiny weight pre-combine: Wc = Wp @ W1 -----------------
__global__ void __launch_bounds__(128) wcomb_kernel(const float* __restrict__ Wp,
                                                    const float* __restrict__ W1,
                                                    float* __restrict__ Wc) {
    __shared__ float srow[D];
    int r = blockIdx.x;
    srow[threadIdx.x] = Wp[r * D + threadIdx.x];
    __syncthreads();
    float acc = 0.f;
    #pragma unroll 8
    for (int k = 0; k < D; k++)
        acc += srow[k] * __ldg(&W1[k * D + threadIdx.x]);
    Wc[r * D + threadIdx.x] = acc;
}

// ------------- fused projection GEMM + bias + relu + row-normalize ----------
// y = relu(xin @ Wc + b), then z = (y - mean)/std(ddof=1), nan->0
// Tile: 32 rows x 128 cols, K=128 in 4 chunks of 32. 256 threads.
__global__ void __launch_bounds__(256) proj_norm_kernel(
    const float* __restrict__ xin, int nrows,
    const float* __restrict__ Wc, const float* __restrict__ bias,
    float* __restrict__ xout) {
    __shared__ float sA[32][128];
    __shared__ float sB[32][128];
    const int row0 = blockIdx.x * 32;
    const int tid  = threadIdx.x;

    // load A tile (32x128), zero-padded past nrows
    #pragma unroll
    for (int i = 0; i < 4; i++) {
        int idx = tid + i * 256;      // float4 index, 0..1023
        int r   = idx >> 5;
        int k4  = idx & 31;
        float4 v = make_float4(0.f, 0.f, 0.f, 0.f);
        if (row0 + r < nrows)
            v = __ldg((const float4*)(xin + (size_t)(row0 + r) * D) + k4);
        *(float4*)&sA[r][k4 * 4] = v;
    }

    const int tr = tid >> 5;   // warp id -> owns rows tr*4..tr*4+3
    const int tc = tid & 31;   // lane -> cols tc*4..tc*4+3
    float acc[4][4] = {};

    for (int kc = 0; kc < 4; kc++) {
        #pragma unroll
        for (int i = 0; i < 4; i++) {
            int idx = tid + i * 256;
            int kk  = idx >> 5;
            int c4  = idx & 31;
            *(float4*)&sB[kk][c4 * 4] =
                __ldg((const float4*)(Wc + (size_t)(kc * 32 + kk) * D) + c4);
        }
        __syncthreads();
        #pragma unroll
        for (int kk = 0; kk < 32; kk++) {
            float a0 = sA[tr * 4 + 0][kc * 32 + kk];
            float a1 = sA[tr * 4 + 1][kc * 32 + kk];
            float a2 = sA[tr * 4 + 2][kc * 32 + kk];
            float a3 = sA[tr * 4 + 3][kc * 32 + kk];
            float4 bv = *(float4*)&sB[kk][tc * 4];
            acc[0][0] += a0 * bv.x; acc[0][1] += a0 * bv.y; acc[0][2] += a0 * bv.z; acc[0][3] += a0 * bv.w;
            acc[1][0] += a1 * bv.x; acc[1][1] += a1 * bv.y; acc[1][2] += a1 * bv.z; acc[1][3] += a1 * bv.w;
            acc[2][0] += a2 * bv.x; acc[2][1] += a2 * bv.y; acc[2][2] += a2 * bv.z; acc[2][3] += a2 * bv.w;
            acc[3][0] += a3 * bv.x; acc[3][1] += a3 * bv.y; acc[3][2] += a3 * bv.z; acc[3][3] += a3 * bv.w;
        }
        __syncthreads();
    }

    // bias + relu
    float4 bv = __ldg((const float4*)bias + tc);
    float bb[4] = {bv.x, bv.y, bv.z, bv.w};
    #pragma unroll
    for (int i = 0; i < 4; i++)
        #pragma unroll
        for (int j = 0; j < 4; j++) {
            float v = acc[i][j] + bb[j];
            acc[i][j] = v > 0.f ? v : 0.f;
        }

    // per-row normalize (row owned by one warp across lanes)
    #pragma unroll
    for (int i = 0; i < 4; i++) {
        float s = acc[i][0] + acc[i][1] + acc[i][2] + acc[i][3];
        float q = acc[i][0]*acc[i][0] + acc[i][1]*acc[i][1]
                + acc[i][2]*acc[i][2] + acc[i][3]*acc[i][3];
        #pragma unroll
        for (int o = 16; o; o >>= 1) {
            s += __shfl_xor_sync(0xffffffffu, s, o);
            q += __shfl_xor_sync(0xffffffffu, q, o);
        }
        float mean = s * (1.f / 128.f);
        float var  = (q - 128.f * mean * mean) * (1.f / 127.f);
        float rstd = (var > 0.f) ? rsqrtf(var) : 0.f;  // var==0 -> all==mean -> 0 (matches nan->0)
        int r = row0 + tr * 4 + i;
        if (r < nrows) {
            float4 o;
            o.x = (acc[i][0] - mean) * rstd;
            o.y = (acc[i][1] - mean) * rstd;
            o.z = (acc[i][2] - mean) * rstd;
            o.w = (acc[i][3] - mean) * rstd;
            *(float4*)(xout + (size_t)r * D + tc * 4) = o;
        }
    }
}

// --------------------------- SpMM: dst[r] += alpha*v*src[c] -----------------
// One warp per edge; lane l handles float4 at column 4l. red.global.add.v4.f32.
__global__ void __launch_bounds__(256) spmm_kernel(
    const int*   __restrict__ rows,
    const int*   __restrict__ cols,
    const float* __restrict__ vals,
    int E,
    const float* __restrict__ src, int src_off,
    float*       __restrict__ dst, int dst_off,
    const float* __restrict__ coe, int cidx) {
    int e = (int)((blockIdx.x * (unsigned)blockDim.x + threadIdx.x) >> 5);
    if (e >= E) return;
    int lane = threadIdx.x & 31;
    float alpha = (cidx >= 0) ? __ldg(&coe[cidx]) : 1.0f;
    int   r = __ldg(&rows[e]) - dst_off;
    int   c = __ldg(&cols[e]) - src_off;
    float v = __ldg(&vals[e]) * alpha;
    float4 h = __ldg((const float4*)(src + (size_t)c * D) + lane);
    float* dp = dst + (size_t)r * D + lane * 4;
    asm volatile("red.global.add.v4.f32 [%0], {%1,%2,%3,%4};"
                 :: "l"(dp), "f"(v * h.x), "f"(v * h.y), "f"(v * h.z), "f"(v * h.w)
                 : "memory");
}

// ----------------- elementwise combine: out = c0*x + c*h --------------------
__global__ void __launch_bounds__(256) combine_kernel(
    const float* __restrict__ x,
    const float* __restrict__ hA,
    const float* __restrict__ hP,
    float* __restrict__ out,
    const float* __restrict__ coe, int cA, int cP) {
    size_t i = (size_t)blockIdx.x * 256 + threadIdx.x;   // float4 index
    if (i >= (size_t)N_TOT * (D / 4)) return;
    size_t row = i >> 5;
    float c0 = __ldg(&coe[0]);
    float4 xv = __ldg((const float4*)x + i);
    float4 hv;
    float  ch;
    if (row < (size_t)N_A) {
        hv = __ldg((const float4*)hA + i);
        ch = __ldg(&coe[cA]);
    } else {
        hv = __ldg((const float4*)hP + (i - (size_t)N_A * (D / 4)));
        ch = __ldg(&coe[cP]);
    }
    float4 o;
    o.x = c0 * xv.x + ch * hv.x;
    o.y = c0 * xv.y + ch * hv.y;
    o.z = c0 * xv.z + ch * hv.z;
    o.w = c0 * xv.w + ch * hv.w;
    ((float4*)out)[i] = o;
}

// --------------------- final GEMM: out = X @ W2 + b2 ------------------------
// Block: 128 threads, 8 rows/block. thread t -> (row t/16, class t%16).
__global__ void __launch_bounds__(128) out_gemm_kernel(
    const float* __restrict__ X, int n,
    const float* __restrict__ W2, const float* __restrict__ b2,
    float* __restrict__ out) {
    __shared__ float sW[D][C_OUT];
    __shared__ float sX[8][D];
    int tid  = threadIdx.x;
    int row0 = blockIdx.x * 8;

    // load W2 (128x16 = 2048 floats): 16 per thread
    #pragma unroll
    for (int i = 0; i < 4; i++) {
        int idx = tid + i * 128;  // float4 index, 0..511
        float4 v = __ldg((const float4*)W2 + idx);
        int k = (idx * 4) >> 4;
        int c = (idx * 4) & 15;
        sW[k][c + 0] = v.x; sW[k][c + 1] = v.y; sW[k][c + 2] = v.z; sW[k][c + 3] = v.w;
    }
    // load 8 rows of X (1024 floats = 256 float4): 2 per thread
    #pragma unroll
    for (int i = 0; i < 2; i++) {
        int idx = tid + i * 128;
        int r = idx >> 5;
        int k4 = idx & 31;
        float4 v = make_float4(0.f, 0.f, 0.f, 0.f);
        if (row0 + r < n)
            v = __ldg((const float4*)(X + (size_t)(row0 + r) * D) + k4);
        *(float4*)&sX[r][k4 * 4] = v;
    }
    __syncthreads();

    int row = tid >> 4;
    int cls = tid & 15;
    float acc = 0.f;
    #pragma unroll 16
    for (int k = 0; k < D; k++)
        acc += sX[row][k] * sW[k][cls];
    if (row0 + row < n)
        out[(size_t)(row0 + row) * C_OUT + cls] = acc + __ldg(&b2[cls]);
}

// ----------------------------------- launch ---------------------------------
extern "C" void kernel_launch(void* const* d_in, const int* in_sizes, int n_in,
                              void* d_out, int out_size) {
    const float* x0      = (const float*)d_in[0];
    const float* x1      = (const float*)d_in[1];
    const float* vals_ap = (const float*)d_in[2];
    const float* vals_pa = (const float*)d_in[3];
    const int*   rows_ap = (const int*)  d_in[4];
    const int*   cols_ap = (const int*)  d_in[5];
    const int*   rows_pa = (const int*)  d_in[6];
    const int*   cols_pa = (const int*)  d_in[7];
    const float* Wp0     = (const float*)d_in[8];
    const float* Wp1     = (const float*)d_in[9];
    const float* W1      = (const float*)d_in[10];
    const float* b1      = (const float*)d_in[11];
    const float* W2      = (const float*)d_in[12];
    const float* b2      = (const float*)d_in[13];
    const float* coe     = (const float*)d_in[14];
    float* out = (float*)d_out;

    const int E1 = in_sizes[2];  // AP edges
    const int E2 = in_sizes[3];  // PA edges

    float *px, *pres, *phA, *phP, *pW0c, *pW1c;
    cudaGetSymbolAddress((void**)&px,   g_x);
    cudaGetSymbolAddress((void**)&pres, g_res);
    cudaGetSymbolAddress((void**)&phA,  g_hA);
    cudaGetSymbolAddress((void**)&phP,  g_hP);
    cudaGetSymbolAddress((void**)&pW0c, g_W0c);
    cudaGetSymbolAddress((void**)&pW1c, g_W1c);

    const int spmm_blocks_ap = (E1 + 7) / 8;   // 8 warps/block, 1 edge/warp
    const int spmm_blocks_pa = (E2 + 7) / 8;
    const int comb_blocks = (int)(((size_t)N_TOT * (D / 4) + 255) / 256);

    // 0) weight pre-combine: Wc = Wp @ W1 (folds first GEMM into projection)
    wcomb_kernel<<<D, D>>>(Wp0, W1, pW0c);
    wcomb_kernel<<<D, D>>>(Wp1, W1, pW1c);

    // 1) fused projection + relu + row-normalize -> g_x
    proj_norm_kernel<<<(N_A + 31) / 32, 256>>>(x0, N_A, pW0c, b1, px);
    proj_norm_kernel<<<(N_P + 31) / 32, 256>>>(x1, N_P, pW1c, b1, px + (size_t)N_A * D);

    // ---------------- pass 1 (first_order = AP, PA) ----------------
    cudaMemsetAsync(phA, 0, (size_t)N_A * D * sizeof(float));
    cudaMemsetAsync(phP, 0, (size_t)N_P * D * sizeof(float));
    // hop1
    spmm_kernel<<<spmm_blocks_ap, 256>>>(rows_ap, cols_ap, vals_ap, E1, px, 0,   phA, 0,   coe, -1);
    spmm_kernel<<<spmm_blocks_pa, 256>>>(rows_pa, cols_pa, vals_pa, E2, px, 0,   phP, N_A, coe, -1);
    // res1 = c0*x + c1*hAP + c2*hPA
    combine_kernel<<<comb_blocks, 256>>>(px, phA, phP, pres, coe, 1, 2);
    // hop2: res1 += c3*AP(hPA) + c4*PA(hAP)
    spmm_kernel<<<spmm_blocks_ap, 256>>>(rows_ap, cols_ap, vals_ap, E1, phP, N_A, pres, 0, coe, 3);
    spmm_kernel<<<spmm_blocks_pa, 256>>>(rows_pa, cols_pa, vals_pa, E2, phA, 0,   pres, 0, coe, 4);

    // ---------------- pass 2 (first_order = PA, AP) ----------------
    cudaMemsetAsync(phA, 0, (size_t)N_A * D * sizeof(float));
    cudaMemsetAsync(phP, 0, (size_t)N_P * D * sizeof(float));
    // hop1 on res1
    spmm_kernel<<<spmm_blocks_ap, 256>>>(rows_ap, cols_ap, vals_ap, E1, pres, 0, phA, 0,   coe, -1);
    spmm_kernel<<<spmm_blocks_pa, 256>>>(rows_pa, cols_pa, vals_pa, E2, pres, 0, phP, N_A, coe, -1);
    // res2 = c0*res1 + c1*hPA + c2*hAP  (coefficient swap vs pass1) -> reuse g_x
    combine_kernel<<<comb_blocks, 256>>>(pres, phA, phP, px, coe, 2, 1);
    // hop2: res2 += c3*PA(hAP) + c4*AP(hPA)
    spmm_kernel<<<spmm_blocks_pa, 256>>>(rows_pa, cols_pa, vals_pa, E2, phA, 0,   px, 0, coe, 3);
    spmm_kernel<<<spmm_blocks_ap, 256>>>(rows_ap, cols_ap, vals_ap, E1, phP, N_A, px, 0, coe, 4);

    // 3) final: out = res2 @ W2 + b2
    out_gemm_kernel<<<(N_TOT + 7) / 8, 128>>>(px, N_TOT, W2, b2, out);
}

// round 2
// speedup vs baseline: 2.1479x; 2.1479x over previous
#include <cuda_runtime.h>
#include <cstddef>
#include <cstdint>

#define N_A   100000
#define N_P   150000
#define N_TOT (N_A + N_P)
#define D     128
#define C_OUT 16
#define EMAX  2000000

// -------------------- device scratch (no allocs allowed) --------------------
__device__ float g_x   [(size_t)N_TOT * D];   // x after proj, later res2
__device__ float g_res [(size_t)N_TOT * D];   // res1
__device__ float g_hA  [(size_t)N_A  * D];
__device__ float g_hP  [(size_t)N_P  * D];
__device__ float g_W0c [D * D];
__device__ float g_W1c [D * D];
// CSR scratch
__device__ int   g_cntA[N_A],     g_cntP[N_P];
__device__ int   g_rpA [N_A + 1], g_rpP [N_P + 1];
__device__ int   g_offA[N_A],     g_offP[N_P];
__device__ int   g_bsumA[256],    g_bsumP[256];
__device__ uint2 g_ecvA[EMAX],    g_ecvP[EMAX];   // (col_adjusted, val bits)

// -------------------- Wc = Wp @ W1 -----------------
__global__ void __launch_bounds__(128) wcomb_kernel(const float* __restrict__ Wp,
                                                    const float* __restrict__ W1,
                                                    float* __restrict__ Wc) {
    __shared__ float srow[D];
    int r = blockIdx.x;
    srow[threadIdx.x] = Wp[r * D + threadIdx.x];
    __syncthreads();
    float acc = 0.f;
    #pragma unroll 8
    for (int k = 0; k < D; k++)
        acc += srow[k] * __ldg(&W1[k * D + threadIdx.x]);
    Wc[r * D + threadIdx.x] = acc;
}

// ------------- fused projection GEMM + bias + relu + row-normalize ----------
__global__ void __launch_bounds__(256) proj_norm_kernel(
    const float* __restrict__ xin, int nrows,
    const float* __restrict__ Wc, const float* __restrict__ bias,
    float* __restrict__ xout) {
    __shared__ float sA[32][128];
    __shared__ float sB[32][128];
    const int row0 = blockIdx.x * 32;
    const int tid  = threadIdx.x;

    #pragma unroll
    for (int i = 0; i < 4; i++) {
        int idx = tid + i * 256;
        int r   = idx >> 5;
        int k4  = idx & 31;
        float4 v = make_float4(0.f, 0.f, 0.f, 0.f);
        if (row0 + r < nrows)
            v = __ldg((const float4*)(xin + (size_t)(row0 + r) * D) + k4);
        *(float4*)&sA[r][k4 * 4] = v;
    }

    const int tr = tid >> 5;
    const int tc = tid & 31;
    float acc[4][4] = {};

    for (int kc = 0; kc < 4; kc++) {
        #pragma unroll
        for (int i = 0; i < 4; i++) {
            int idx = tid + i * 256;
            int kk  = idx >> 5;
            int c4  = idx & 31;
            *(float4*)&sB[kk][c4 * 4] =
                __ldg((const float4*)(Wc + (size_t)(kc * 32 + kk) * D) + c4);
        }
        __syncthreads();
        #pragma unroll
        for (int kk = 0; kk < 32; kk++) {
            float a0 = sA[tr * 4 + 0][kc * 32 + kk];
            float a1 = sA[tr * 4 + 1][kc * 32 + kk];
            float a2 = sA[tr * 4 + 2][kc * 32 + kk];
            float a3 = sA[tr * 4 + 3][kc * 32 + kk];
            float4 bv = *(float4*)&sB[kk][tc * 4];
            acc[0][0] += a0 * bv.x; acc[0][1] += a0 * bv.y; acc[0][2] += a0 * bv.z; acc[0][3] += a0 * bv.w;
            acc[1][0] += a1 * bv.x; acc[1][1] += a1 * bv.y; acc[1][2] += a1 * bv.z; acc[1][3] += a1 * bv.w;
            acc[2][0] += a2 * bv.x; acc[2][1] += a2 * bv.y; acc[2][2] += a2 * bv.z; acc[2][3] += a2 * bv.w;
            acc[3][0] += a3 * bv.x; acc[3][1] += a3 * bv.y; acc[3][2] += a3 * bv.z; acc[3][3] += a3 * bv.w;
        }
        __syncthreads();
    }

    float4 bv = __ldg((const float4*)bias + tc);
    float bb[4] = {bv.x, bv.y, bv.z, bv.w};
    #pragma unroll
    for (int i = 0; i < 4; i++)
        #pragma unroll
        for (int j = 0; j < 4; j++) {
            float v = acc[i][j] + bb[j];
            acc[i][j] = v > 0.f ? v : 0.f;
        }

    #pragma unroll
    for (int i = 0; i < 4; i++) {
        float s = acc[i][0] + acc[i][1] + acc[i][2] + acc[i][3];
        float q = acc[i][0]*acc[i][0] + acc[i][1]*acc[i][1]
                + acc[i][2]*acc[i][2] + acc[i][3]*acc[i][3];
        #pragma unroll
        for (int o = 16; o; o >>= 1) {
            s += __shfl_xor_sync(0xffffffffu, s, o);
            q += __shfl_xor_sync(0xffffffffu, q, o);
        }
        float mean = s * (1.f / 128.f);
        float var  = (q - 128.f * mean * mean) * (1.f / 127.f);
        float rstd = (var > 0.f) ? rsqrtf(var) : 0.f;
        int r = row0 + tr * 4 + i;
        if (r < nrows) {
            float4 o;
            o.x = (acc[i][0] - mean) * rstd;
            o.y = (acc[i][1] - mean) * rstd;
            o.z = (acc[i][2] - mean) * rstd;
            o.w = (acc[i][3] - mean) * rstd;
            *(float4*)(xout + (size_t)r * D + tc * 4) = o;
        }
    }
}

// ------------------------------ CSR build -----------------------------------
__global__ void __launch_bounds__(256) hist_kernel(const int* __restrict__ rows, int E,
                                                   int* __restrict__ cnt, int roff) {
    int i = blockIdx.x * 256 + threadIdx.x;
    if (i < E) atomicAdd(&cnt[__ldg(&rows[i]) - roff], 1);
}

// chunk = 2048 elems/block (256 thr x 8)
__global__ void __launch_bounds__(256) scan1_kernel(const int* __restrict__ cnt, int n,
                                                    int* __restrict__ rp, int* __restrict__ bsum) {
    __shared__ int wsum[8];
    const int base = blockIdx.x * 2048;
    const int t = threadIdx.x;
    int v[8]; int s = 0;
    #pragma unroll
    for (int i = 0; i < 8; i++) {
        int idx = base + t * 8 + i;
        int c = (idx < n) ? __ldg(&cnt[idx]) : 0;
        v[i] = s; s += c;
    }
    int lane = t & 31, w = t >> 5;
    int p = s;
    #pragma unroll
    for (int o = 1; o < 32; o <<= 1) {
        int q = __shfl_up_sync(0xffffffffu, p, o);
        if (lane >= o) p += q;
    }
    if (lane == 31) wsum[w] = p;
    __syncthreads();
    if (t < 8) {
        int ws = wsum[t];
        int pp = ws;
        #pragma unroll
        for (int o = 1; o < 8; o <<= 1) {
            int q = __shfl_up_sync(0xffu, pp, o);
            if (t >= o) pp += q;
        }
        wsum[t] = pp - ws;          // exclusive over warps
        if (t == 7) bsum[blockIdx.x] = pp;  // block total
    }
    __syncthreads();
    int texcl = (p - s) + wsum[w];
    #pragma unroll
    for (int i = 0; i < 8; i++) {
        int idx = base + t * 8 + i;
        if (idx < n) rp[idx] = texcl + v[i];
    }
}

__global__ void __launch_bounds__(256) scan2_kernel(int* __restrict__ bsum, int nb) {
    __shared__ int sh[256];
    int t = threadIdx.x;
    int v = (t < nb) ? bsum[t] : 0;
    sh[t] = v; __syncthreads();
    #pragma unroll
    for (int o = 1; o < 256; o <<= 1) {
        int q = (t >= o) ? sh[t - o] : 0;
        __syncthreads();
        sh[t] += q;
        __syncthreads();
    }
    if (t < nb) bsum[t] = sh[t] - v;   // exclusive
}

__global__ void __launch_bounds__(256) scan3_kernel(const int* __restrict__ bsum, int n,
                                                    int* __restrict__ rp, int* __restrict__ offs,
                                                    const int* __restrict__ cnt) {
    int idx = blockIdx.x * 256 + threadIdx.x;
    if (idx < n) {
        int v = rp[idx] + __ldg(&bsum[idx >> 11]);
        rp[idx] = v;
        offs[idx] = v;
        if (idx == n - 1) rp[n] = v + __ldg(&cnt[idx]);
    }
}

__global__ void __launch_bounds__(256) scatter_kernel(
    const int* __restrict__ rows, const int* __restrict__ cols,
    const float* __restrict__ vals, int E,
    int* __restrict__ offs, uint2* __restrict__ ecv, int roff, int coff) {
    int i = blockIdx.x * 256 + threadIdx.x;
    if (i >= E) return;
    int r = __ldg(&rows[i]) - roff;
    int pos = atomicAdd(&offs[r], 1);
    ecv[pos] = make_uint2((unsigned)(__ldg(&cols[i]) - coff), __float_as_uint(__ldg(&vals[i])));
}

// ----------------------------- CSR SpMM (hop 1) -----------------------------
// one warp per row: dst[r] = sum_e v * src[col]
__global__ void __launch_bounds__(256) spmm_csr_kernel(
    const int* __restrict__ rp, const uint2* __restrict__ ecv,
    const float* __restrict__ src, float* __restrict__ dst, int nrows) {
    int r = (int)((blockIdx.x * 256u + threadIdx.x) >> 5);
    if (r >= nrows) return;
    int lane = threadIdx.x & 31;
    int s = __ldg(&rp[r]), e = __ldg(&rp[r + 1]);
    float4 a0 = {0, 0, 0, 0}, a1 = {0, 0, 0, 0};
    int i = s;
    for (; i + 2 <= e; i += 2) {
        uint2 p0 = __ldg(&ecv[i]);
        uint2 p1 = __ldg(&ecv[i + 1]);
        float4 h0 = __ldg((const float4*)(src + (size_t)p0.x * D) + lane);
        float4 h1 = __ldg((const float4*)(src + (size_t)p1.x * D) + lane);
        float v0 = __uint_as_float(p0.y), v1 = __uint_as_float(p1.y);
        a0.x += v0 * h0.x; a0.y += v0 * h0.y; a0.z += v0 * h0.z; a0.w += v0 * h0.w;
        a1.x += v1 * h1.x; a1.y += v1 * h1.y; a1.z += v1 * h1.z; a1.w += v1 * h1.w;
    }
    if (i < e) {
        uint2 p0 = __ldg(&ecv[i]);
        float4 h0 = __ldg((const float4*)(src + (size_t)p0.x * D) + lane);
        float v0 = __uint_as_float(p0.y);
        a0.x += v0 * h0.x; a0.y += v0 * h0.y; a0.z += v0 * h0.z; a0.w += v0 * h0.w;
    }
    float4 o;
    o.x = a0.x + a1.x; o.y = a0.y + a1.y; o.z = a0.z + a1.z; o.w = a0.w + a1.w;
    *((float4*)(dst + (size_t)r * D) + lane) = o;
}

// ------------------- CSR SpMM hop-2 fused with combine ----------------------
// res[R] = c0*x[R] + c_own*hown[r] + c_hop*sum_e v*hsrc[col]
__global__ void __launch_bounds__(256) spmm_csr_fused_kernel(
    const int* __restrict__ rp, const uint2* __restrict__ ecv,
    const float* __restrict__ hsrc,
    const float* __restrict__ xbase, const float* __restrict__ hown,
    float* __restrict__ resbase, int nrows, int row_off,
    const float* __restrict__ coe, int c_own, int c_hop) {
    int r = (int)((blockIdx.x * 256u + threadIdx.x) >> 5);
    if (r >= nrows) return;
    int lane = threadIdx.x & 31;
    int s = __ldg(&rp[r]), e = __ldg(&rp[r + 1]);
    float4 a0 = {0, 0, 0, 0}, a1 = {0, 0, 0, 0};
    int i = s;
    for (; i + 2 <= e; i += 2) {
        uint2 p0 = __ldg(&ecv[i]);
        uint2 p1 = __ldg(&ecv[i + 1]);
        float4 h0 = __ldg((const float4*)(hsrc + (size_t)p0.x * D) + lane);
        float4 h1 = __ldg((const float4*)(hsrc + (size_t)p1.x * D) + lane);
        float v0 = __uint_as_float(p0.y), v1 = __uint_as_float(p1.y);
        a0.x += v0 * h0.x; a0.y += v0 * h0.y; a0.z += v0 * h0.z; a0.w += v0 * h0.w;
        a1.x += v1 * h1.x; a1.y += v1 * h1.y; a1.z += v1 * h1.z; a1.w += v1 * h1.w;
    }
    if (i < e) {
        uint2 p0 = __ldg(&ecv[i]);
        float4 h0 = __ldg((const float4*)(hsrc + (size_t)p0.x * D) + lane);
        float v0 = __uint_as_float(p0.y);
        a0.x += v0 * h0.x; a0.y += v0 * h0.y; a0.z += v0 * h0.z; a0.w += v0 * h0.w;
    }
    size_t R = (size_t)(r + row_off);
    float c0 = __ldg(&coe[0]);
    float cw = __ldg(&coe[c_own]);
    float ch = __ldg(&coe[c_hop]);
    float4 xv = __ldg((const float4*)(xbase + R * D) + lane);
    float4 hv = __ldg((const float4*)(hown + (size_t)r * D) + lane);
    float4 o;
    o.x = c0 * xv.x + cw * hv.x + ch * (a0.x + a1.x);
    o.y = c0 * xv.y + cw * hv.y + ch * (a0.y + a1.y);
    o.z = c0 * xv.z + cw * hv.z + ch * (a0.z + a1.z);
    o.w = c0 * xv.w + cw * hv.w + ch * (a0.w + a1.w);
    *((float4*)(resbase + R * D) + lane) = o;
}

// --------------------- final GEMM: out = X @ W2 + b2 ------------------------
__global__ void __launch_bounds__(128) out_gemm_kernel(
    const float* __restrict__ X, int n,
    const float* __restrict__ W2, const float* __restrict__ b2,
    float* __restrict__ out) {
    __shared__ float sW[D][C_OUT];
    __shared__ float sX[8][D];
    int tid  = threadIdx.x;
    int row0 = blockIdx.x * 8;

    #pragma unroll
    for (int i = 0; i < 4; i++) {
        int idx = tid + i * 128;
        float4 v = __ldg((const float4*)W2 + idx);
        int k = (idx * 4) >> 4;
        int c = (idx * 4) & 15;
        sW[k][c + 0] = v.x; sW[k][c + 1] = v.y; sW[k][c + 2] = v.z; sW[k][c + 3] = v.w;
    }
    #pragma unroll
    for (int i = 0; i < 2; i++) {
        int idx = tid + i * 128;
        int r = idx >> 5;
        int k4 = idx & 31;
        float4 v = make_float4(0.f, 0.f, 0.f, 0.f);
        if (row0 + r < n)
            v = __ldg((const float4*)(X + (size_t)(row0 + r) * D) + k4);
        *(float4*)&sX[r][k4 * 4] = v;
    }
    __syncthreads();

    int row = tid >> 4;
    int cls = tid & 15;
    float acc = 0.f;
    #pragma unroll 16
    for (int k = 0; k < D; k++)
        acc += sX[row][k] * sW[k][cls];
    if (row0 + row < n)
        out[(size_t)(row0 + row) * C_OUT + cls] = acc + __ldg(&b2[cls]);
}

// ----------------------------------- launch ---------------------------------
extern "C" void kernel_launch(void* const* d_in, const int* in_sizes, int n_in,
                              void* d_out, int out_size) {
    const float* x0      = (const float*)d_in[0];
    const float* x1      = (const float*)d_in[1];
    const float* vals_ap = (const float*)d_in[2];
    const float* vals_pa = (const float*)d_in[3];
    const int*   rows_ap = (const int*)  d_in[4];
    const int*   cols_ap = (const int*)  d_in[5];
    const int*   rows_pa = (const int*)  d_in[6];
    const int*   cols_pa = (const int*)  d_in[7];
    const float* Wp0     = (const float*)d_in[8];
    const float* Wp1     = (const float*)d_in[9];
    const float* W1      = (const float*)d_in[10];
    const float* b1      = (const float*)d_in[11];
    const float* W2      = (const float*)d_in[12];
    const float* b2      = (const float*)d_in[13];
    const float* coe     = (const float*)d_in[14];
    float* out = (float*)d_out;

    const int E1 = in_sizes[2];
    const int E2 = in_sizes[3];

    float *px, *pres, *phA, *phP, *pW0c, *pW1c;
    int *pcntA, *pcntP, *prpA, *prpP, *poffA, *poffP, *pbA, *pbP;
    uint2 *pecvA, *pecvP;
    cudaGetSymbolAddress((void**)&px,    g_x);
    cudaGetSymbolAddress((void**)&pres,  g_res);
    cudaGetSymbolAddress((void**)&phA,   g_hA);
    cudaGetSymbolAddress((void**)&phP,   g_hP);
    cudaGetSymbolAddress((void**)&pW0c,  g_W0c);
    cudaGetSymbolAddress((void**)&pW1c,  g_W1c);
    cudaGetSymbolAddress((void**)&pcntA, g_cntA);
    cudaGetSymbolAddress((void**)&pcntP, g_cntP);
    cudaGetSymbolAddress((void**)&prpA,  g_rpA);
    cudaGetSymbolAddress((void**)&prpP,  g_rpP);
    cudaGetSymbolAddress((void**)&poffA, g_offA);
    cudaGetSymbolAddress((void**)&poffP, g_offP);
    cudaGetSymbolAddress((void**)&pbA,   g_bsumA);
    cudaGetSymbolAddress((void**)&pbP,   g_bsumP);
    cudaGetSymbolAddress((void**)&pecvA, g_ecvA);
    cudaGetSymbolAddress((void**)&pecvP, g_ecvP);

    const int nbA = (N_A + 2047) / 2048;
    const int nbP = (N_P + 2047) / 2048;
    const int gA = (N_A * 32 + 255) / 256;   // spmm grids (warp per row)
    const int gP = (N_P * 32 + 255) / 256;

    // 0) weight pre-combine + fused projection/relu/normalize
    wcomb_kernel<<<D, D>>>(Wp0, W1, pW0c);
    wcomb_kernel<<<D, D>>>(Wp1, W1, pW1c);
    proj_norm_kernel<<<(N_A + 31) / 32, 256>>>(x0, N_A, pW0c, b1, px);
    proj_norm_kernel<<<(N_P + 31) / 32, 256>>>(x1, N_P, pW1c, b1, px + (size_t)N_A * D);

    // 1) CSR build (once, reused by all 8 SpMMs)
    cudaMemsetAsync(pcntA, 0, N_A * sizeof(int));
    cudaMemsetAsync(pcntP, 0, N_P * sizeof(int));
    hist_kernel<<<(E1 + 255) / 256, 256>>>(rows_ap, E1, pcntA, 0);
    hist_kernel<<<(E2 + 255) / 256, 256>>>(rows_pa, E2, pcntP, N_A);
    scan1_kernel<<<nbA, 256>>>(pcntA, N_A, prpA, pbA);
    scan1_kernel<<<nbP, 256>>>(pcntP, N_P, prpP, pbP);
    scan2_kernel<<<1, 256>>>(pbA, nbA);
    scan2_kernel<<<1, 256>>>(pbP, nbP);
    scan3_kernel<<<(N_A + 255) / 256, 256>>>(pbA, N_A, prpA, poffA, pcntA);
    scan3_kernel<<<(N_P + 255) / 256, 256>>>(pbP, N_P, prpP, poffP, pcntP);
    // AP cols stored as col-N_A (P-local); PA cols raw (A-local)
    scatter_kernel<<<(E1 + 255) / 256, 256>>>(rows_ap, cols_ap, vals_ap, E1, poffA, pecvA, 0,   N_A);
    scatter_kernel<<<(E2 + 255) / 256, 256>>>(rows_pa, cols_pa, vals_pa, E2, poffP, pecvP, N_A, 0);

    // ---------------- pass 1 (first_order = AP, PA) ----------------
    // hop1: hA = AP(x), hP = PA(x)
    spmm_csr_kernel<<<gA, 256>>>(prpA, pecvA, px + (size_t)N_A * D, phA, N_A);
    spmm_csr_kernel<<<gP, 256>>>(prpP, pecvP, px,                   phP, N_P);
    // hop2 + combine: res1 rows
    spmm_csr_fused_kernel<<<gA, 256>>>(prpA, pecvA, phP, px, phA, pres, N_A, 0,   coe, 1, 3);
    spmm_csr_fused_kernel<<<gP, 256>>>(prpP, pecvP, phA, px, phP, pres, N_P, N_A, coe, 2, 4);

    // ---------------- pass 2 (first_order = PA, AP) ----------------
    spmm_csr_kernel<<<gA, 256>>>(prpA, pecvA, pres + (size_t)N_A * D, phA, N_A);
    spmm_csr_kernel<<<gP, 256>>>(prpP, pecvP, pres,                   phP, N_P);
    // coefficient swap vs pass 1
    spmm_csr_fused_kernel<<<gA, 256>>>(prpA, pecvA, phP, pres, phA, px, N_A, 0,   coe, 2, 4);
    spmm_csr_fused_kernel<<<gP, 256>>>(prpP, pecvP, phA, pres, phP, px, N_P, N_A, coe, 1, 3);

    // 3) out = res2 @ W2 + b2
    out_gemm_kernel<<<(N_TOT + 7) / 8, 128>>>(px, N_TOT, W2, b2, out);
}

// round 3
// speedup vs baseline: 2.3388x; 1.0889x over previous
#include <cuda_runtime.h>
#include <cuda_bf16.h>
#include <cstddef>
#include <cstdint>

#define N_A   100000
#define N_P   150000
#define N_TOT (N_A + N_P)
#define D     128
#define C_OUT 16
#define EMAX  2000000

// -------------------- device scratch (no allocs allowed) --------------------
__device__ float g_x   [(size_t)N_TOT * D];   // fp32 x after proj (spine)
__device__ float g_res [(size_t)N_TOT * D];   // fp32 res1 (spine)
__device__ uint2 g_xh  [(size_t)N_TOT * 32];  // bf16x4 shadow of x
__device__ uint2 g_resh[(size_t)N_TOT * 32];  // bf16x4 shadow of res1
__device__ uint2 g_hA  [(size_t)N_A  * 32];   // bf16x4 hop-1 output (A rows)
__device__ uint2 g_hP  [(size_t)N_P  * 32];   // bf16x4 hop-1 output (P rows)
__device__ float g_W0c [D * D];
__device__ float g_W1c [D * D];
// CSR scratch
__device__ int   g_cntA[N_A],     g_cntP[N_P];
__device__ int   g_rpA [N_A + 1], g_rpP [N_P + 1];
__device__ int   g_offA[N_A],     g_offP[N_P];
__device__ int   g_bsumA[256],    g_bsumP[256];
__device__ uint2 g_ecvA[EMAX],    g_ecvP[EMAX];   // (col_local, val bits)

// ----------------------------- bf16x4 helpers -------------------------------
__device__ __forceinline__ float4 ldg_bf16x4(const uint2* p) {
    uint2 r = __ldg(p);
    __nv_bfloat162 a = *reinterpret_cast<const __nv_bfloat162*>(&r.x);
    __nv_bfloat162 b = *reinterpret_cast<const __nv_bfloat162*>(&r.y);
    float2 f0 = __bfloat1622float2(a);
    float2 f1 = __bfloat1622float2(b);
    return make_float4(f0.x, f0.y, f1.x, f1.y);
}
__device__ __forceinline__ uint2 pack_bf16x4(float4 v) {
    __nv_bfloat162 a = __floats2bfloat162_rn(v.x, v.y);
    __nv_bfloat162 b = __floats2bfloat162_rn(v.z, v.w);
    uint2 r;
    r.x = *reinterpret_cast<const uint32_t*>(&a);
    r.y = *reinterpret_cast<const uint32_t*>(&b);
    return r;
}

// -------------------- Wc = Wp @ W1 -----------------
__global__ void __launch_bounds__(128) wcomb_kernel(const float* __restrict__ Wp,
                                                    const float* __restrict__ W1,
                                                    float* __restrict__ Wc) {
    __shared__ float srow[D];
    int r = blockIdx.x;
    srow[threadIdx.x] = Wp[r * D + threadIdx.x];
    __syncthreads();
    float acc = 0.f;
    #pragma unroll 8
    for (int k = 0; k < D; k++)
        acc += srow[k] * __ldg(&W1[k * D + threadIdx.x]);
    Wc[r * D + threadIdx.x] = acc;
}

// ------------- fused projection GEMM + bias + relu + row-normalize ----------
// writes fp32 x and bf16 shadow
__global__ void __launch_bounds__(256) proj_norm_kernel(
    const float* __restrict__ xin, int nrows,
    const float* __restrict__ Wc, const float* __restrict__ bias,
    float* __restrict__ xout, uint2* __restrict__ xout_h) {
    __shared__ float sA[32][128];
    __shared__ float sB[32][128];
    const int row0 = blockIdx.x * 32;
    const int tid  = threadIdx.x;

    #pragma unroll
    for (int i = 0; i < 4; i++) {
        int idx = tid + i * 256;
        int r   = idx >> 5;
        int k4  = idx & 31;
        float4 v = make_float4(0.f, 0.f, 0.f, 0.f);
        if (row0 + r < nrows)
            v = __ldg((const float4*)(xin + (size_t)(row0 + r) * D) + k4);
        *(float4*)&sA[r][k4 * 4] = v;
    }

    const int tr = tid >> 5;
    const int tc = tid & 31;
    float acc[4][4] = {};

    for (int kc = 0; kc < 4; kc++) {
        #pragma unroll
        for (int i = 0; i < 4; i++) {
            int idx = tid + i * 256;
            int kk  = idx >> 5;
            int c4  = idx & 31;
            *(float4*)&sB[kk][c4 * 4] =
                __ldg((const float4*)(Wc + (size_t)(kc * 32 + kk) * D) + c4);
        }
        __syncthreads();
        #pragma unroll
        for (int kk = 0; kk < 32; kk++) {
            float a0 = sA[tr * 4 + 0][kc * 32 + kk];
            float a1 = sA[tr * 4 + 1][kc * 32 + kk];
            float a2 = sA[tr * 4 + 2][kc * 32 + kk];
            float a3 = sA[tr * 4 + 3][kc * 32 + kk];
            float4 bv = *(float4*)&sB[kk][tc * 4];
            acc[0][0] += a0 * bv.x; acc[0][1] += a0 * bv.y; acc[0][2] += a0 * bv.z; acc[0][3] += a0 * bv.w;
            acc[1][0] += a1 * bv.x; acc[1][1] += a1 * bv.y; acc[1][2] += a1 * bv.z; acc[1][3] += a1 * bv.w;
            acc[2][0] += a2 * bv.x; acc[2][1] += a2 * bv.y; acc[2][2] += a2 * bv.z; acc[2][3] += a2 * bv.w;
            acc[3][0] += a3 * bv.x; acc[3][1] += a3 * bv.y; acc[3][2] += a3 * bv.z; acc[3][3] += a3 * bv.w;
        }
        __syncthreads();
    }

    float4 bv = __ldg((const float4*)bias + tc);
    float bb[4] = {bv.x, bv.y, bv.z, bv.w};
    #pragma unroll
    for (int i = 0; i < 4; i++)
        #pragma unroll
        for (int j = 0; j < 4; j++) {
            float v = acc[i][j] + bb[j];
            acc[i][j] = v > 0.f ? v : 0.f;
        }

    #pragma unroll
    for (int i = 0; i < 4; i++) {
        float s = acc[i][0] + acc[i][1] + acc[i][2] + acc[i][3];
        float q = acc[i][0]*acc[i][0] + acc[i][1]*acc[i][1]
                + acc[i][2]*acc[i][2] + acc[i][3]*acc[i][3];
        #pragma unroll
        for (int o = 16; o; o >>= 1) {
            s += __shfl_xor_sync(0xffffffffu, s, o);
            q += __shfl_xor_sync(0xffffffffu, q, o);
        }
        float mean = s * (1.f / 128.f);
        float var  = (q - 128.f * mean * mean) * (1.f / 127.f);
        float rstd = (var > 0.f) ? rsqrtf(var) : 0.f;
        int r = row0 + tr * 4 + i;
        if (r < nrows) {
            float4 o;
            o.x = (acc[i][0] - mean) * rstd;
            o.y = (acc[i][1] - mean) * rstd;
            o.z = (acc[i][2] - mean) * rstd;
            o.w = (acc[i][3] - mean) * rstd;
            *(float4*)(xout + (size_t)r * D + tc * 4) = o;
            xout_h[(size_t)r * 32 + tc] = pack_bf16x4(o);
        }
    }
}

// ------------------------------ CSR build -----------------------------------
__global__ void __launch_bounds__(256) hist_kernel(const int* __restrict__ rows, int E,
                                                   int* __restrict__ cnt, int roff) {
    int i = blockIdx.x * 256 + threadIdx.x;
    if (i < E) atomicAdd(&cnt[__ldg(&rows[i]) - roff], 1);
}

__global__ void __launch_bounds__(256) scan1_kernel(const int* __restrict__ cnt, int n,
                                                    int* __restrict__ rp, int* __restrict__ bsum) {
    __shared__ int wsum[8];
    const int base = blockIdx.x * 2048;
    const int t = threadIdx.x;
    int v[8]; int s = 0;
    #pragma unroll
    for (int i = 0; i < 8; i++) {
        int idx = base + t * 8 + i;
        int c = (idx < n) ? __ldg(&cnt[idx]) : 0;
        v[i] = s; s += c;
    }
    int lane = t & 31, w = t >> 5;
    int p = s;
    #pragma unroll
    for (int o = 1; o < 32; o <<= 1) {
        int q = __shfl_up_sync(0xffffffffu, p, o);
        if (lane >= o) p += q;
    }
    if (lane == 31) wsum[w] = p;
    __syncthreads();
    if (t < 8) {
        int ws = wsum[t];
        int pp = ws;
        #pragma unroll
        for (int o = 1; o < 8; o <<= 1) {
            int q = __shfl_up_sync(0xffu, pp, o);
            if (t >= o) pp += q;
        }
        wsum[t] = pp - ws;
        if (t == 7) bsum[blockIdx.x] = pp;
    }
    __syncthreads();
    int texcl = (p - s) + wsum[w];
    #pragma unroll
    for (int i = 0; i < 8; i++) {
        int idx = base + t * 8 + i;
        if (idx < n) rp[idx] = texcl + v[i];
    }
}

__global__ void __launch_bounds__(256) scan2_kernel(int* __restrict__ bsum, int nb) {
    __shared__ int sh[256];
    int t = threadIdx.x;
    int v = (t < nb) ? bsum[t] : 0;
    sh[t] = v; __syncthreads();
    #pragma unroll
    for (int o = 1; o < 256; o <<= 1) {
        int q = (t >= o) ? sh[t - o] : 0;
        __syncthreads();
        sh[t] += q;
        __syncthreads();
    }
    if (t < nb) bsum[t] = sh[t] - v;
}

__global__ void __launch_bounds__(256) scan3_kernel(const int* __restrict__ bsum, int n,
                                                    int* __restrict__ rp, int* __restrict__ offs,
                                                    const int* __restrict__ cnt) {
    int idx = blockIdx.x * 256 + threadIdx.x;
    if (idx < n) {
        int v = rp[idx] + __ldg(&bsum[idx >> 11]);
        rp[idx] = v;
        offs[idx] = v;
        if (idx == n - 1) rp[n] = v + __ldg(&cnt[idx]);
    }
}

__global__ void __launch_bounds__(256) scatter_kernel(
    const int* __restrict__ rows, const int* __restrict__ cols,
    const float* __restrict__ vals, int E,
    int* __restrict__ offs, uint2* __restrict__ ecv, int roff, int coff) {
    int i = blockIdx.x * 256 + threadIdx.x;
    if (i >= E) return;
    int r = __ldg(&rows[i]) - roff;
    int pos = atomicAdd(&offs[r], 1);
    ecv[pos] = make_uint2((unsigned)(__ldg(&cols[i]) - coff), __float_as_uint(__ldg(&vals[i])));
}

// ----------------------------- CSR SpMM (hop 1) -----------------------------
// one warp per row: dst[r] = sum_e v * src_bf16[col];  src/dst are bf16x4 rows of 32 uint2
__global__ void __launch_bounds__(256) spmm_csr_kernel(
    const int* __restrict__ rp, const uint2* __restrict__ ecv,
    const uint2* __restrict__ src, uint2* __restrict__ dst, int nrows) {
    int r = (int)((blockIdx.x * 256u + threadIdx.x) >> 5);
    if (r >= nrows) return;
    int lane = threadIdx.x & 31;
    int s = __ldg(&rp[r]), e = __ldg(&rp[r + 1]);
    float4 a0 = {0, 0, 0, 0}, a1 = {0, 0, 0, 0};
    int i = s;
    for (; i + 2 <= e; i += 2) {
        uint2 p0 = __ldg(&ecv[i]);
        uint2 p1 = __ldg(&ecv[i + 1]);
        float4 h0 = ldg_bf16x4(src + (size_t)p0.x * 32 + lane);
        float4 h1 = ldg_bf16x4(src + (size_t)p1.x * 32 + lane);
        float v0 = __uint_as_float(p0.y), v1 = __uint_as_float(p1.y);
        a0.x += v0 * h0.x; a0.y += v0 * h0.y; a0.z += v0 * h0.z; a0.w += v0 * h0.w;
        a1.x += v1 * h1.x; a1.y += v1 * h1.y; a1.z += v1 * h1.z; a1.w += v1 * h1.w;
    }
    if (i < e) {
        uint2 p0 = __ldg(&ecv[i]);
        float4 h0 = ldg_bf16x4(src + (size_t)p0.x * 32 + lane);
        float v0 = __uint_as_float(p0.y);
        a0.x += v0 * h0.x; a0.y += v0 * h0.y; a0.z += v0 * h0.z; a0.w += v0 * h0.w;
    }
    float4 o;
    o.x = a0.x + a1.x; o.y = a0.y + a1.y; o.z = a0.z + a1.z; o.w = a0.w + a1.w;
    dst[(size_t)r * 32 + lane] = pack_bf16x4(o);
}

// ------------------- pass-1 hop-2 fused with combine ------------------------
// res[R] = c0*x[R] + c_own*hown[r] + c_hop*sum v*hsrc[col]; also bf16 shadow
__global__ void __launch_bounds__(256) spmm_csr_fused_kernel(
    const int* __restrict__ rp, const uint2* __restrict__ ecv,
    const uint2* __restrict__ hsrc,
    const float* __restrict__ xbase, const uint2* __restrict__ hown,
    float* __restrict__ resbase, uint2* __restrict__ resh,
    int nrows, int row_off,
    const float* __restrict__ coe, int c_own, int c_hop) {
    int r = (int)((blockIdx.x * 256u + threadIdx.x) >> 5);
    if (r >= nrows) return;
    int lane = threadIdx.x & 31;
    int s = __ldg(&rp[r]), e = __ldg(&rp[r + 1]);
    float4 a0 = {0, 0, 0, 0}, a1 = {0, 0, 0, 0};
    int i = s;
    for (; i + 2 <= e; i += 2) {
        uint2 p0 = __ldg(&ecv[i]);
        uint2 p1 = __ldg(&ecv[i + 1]);
        float4 h0 = ldg_bf16x4(hsrc + (size_t)p0.x * 32 + lane);
        float4 h1 = ldg_bf16x4(hsrc + (size_t)p1.x * 32 + lane);
        float v0 = __uint_as_float(p0.y), v1 = __uint_as_float(p1.y);
        a0.x += v0 * h0.x; a0.y += v0 * h0.y; a0.z += v0 * h0.z; a0.w += v0 * h0.w;
        a1.x += v1 * h1.x; a1.y += v1 * h1.y; a1.z += v1 * h1.z; a1.w += v1 * h1.w;
    }
    if (i < e) {
        uint2 p0 = __ldg(&ecv[i]);
        float4 h0 = ldg_bf16x4(hsrc + (size_t)p0.x * 32 + lane);
        float v0 = __uint_as_float(p0.y);
        a0.x += v0 * h0.x; a0.y += v0 * h0.y; a0.z += v0 * h0.z; a0.w += v0 * h0.w;
    }
    size_t R = (size_t)(r + row_off);
    float c0 = __ldg(&coe[0]);
    float cw = __ldg(&coe[c_own]);
    float ch = __ldg(&coe[c_hop]);
    float4 xv = __ldg((const float4*)(xbase + R * D) + lane);
    float4 hv = ldg_bf16x4(hown + (size_t)r * 32 + lane);
    float4 o;
    o.x = c0 * xv.x + cw * hv.x + ch * (a0.x + a1.x);
    o.y = c0 * xv.y + cw * hv.y + ch * (a0.y + a1.y);
    o.z = c0 * xv.z + cw * hv.z + ch * (a0.z + a1.z);
    o.w = c0 * xv.w + cw * hv.w + ch * (a0.w + a1.w);
    *((float4*)(resbase + R * D) + lane) = o;
    resh[R * 32 + lane] = pack_bf16x4(o);
}

// ----------- pass-2 hop-2 fused with combine AND output GEMM ----------------
// out[R,:] = (c0*res1[R] + c_own*hown[r] + c_hop*sum v*hsrc[col]) @ W2 + b2
__global__ void __launch_bounds__(256) spmm_csr_fused_out_kernel(
    const int* __restrict__ rp, const uint2* __restrict__ ecv,
    const uint2* __restrict__ hsrc,
    const float* __restrict__ xbase, const uint2* __restrict__ hown,
    float* __restrict__ out, int nrows, int row_off,
    const float* __restrict__ coe, int c_own, int c_hop,
    const float* __restrict__ W2, const float* __restrict__ b2) {
    __shared__ float sW[C_OUT][D];   // class-major for conflict-free float4 LDS
    __shared__ float sb2[C_OUT];
    int tid = threadIdx.x;
    for (int i = tid; i < C_OUT * D; i += 256) {
        int c = i >> 7, k = i & 127;
        sW[c][k] = __ldg(&W2[k * C_OUT + c]);
    }
    if (tid < C_OUT) sb2[tid] = __ldg(&b2[tid]);
    __syncthreads();

    int r = (int)((blockIdx.x * 256u + tid) >> 5);
    if (r >= nrows) return;
    int lane = tid & 31;
    int s = __ldg(&rp[r]), e = __ldg(&rp[r + 1]);
    float4 a0 = {0, 0, 0, 0}, a1 = {0, 0, 0, 0};
    int i = s;
    for (; i + 2 <= e; i += 2) {
        uint2 p0 = __ldg(&ecv[i]);
        uint2 p1 = __ldg(&ecv[i + 1]);
        float4 h0 = ldg_bf16x4(hsrc + (size_t)p0.x * 32 + lane);
        float4 h1 = ldg_bf16x4(hsrc + (size_t)p1.x * 32 + lane);
        float v0 = __uint_as_float(p0.y), v1 = __uint_as_float(p1.y);
        a0.x += v0 * h0.x; a0.y += v0 * h0.y; a0.z += v0 * h0.z; a0.w += v0 * h0.w;
        a1.x += v1 * h1.x; a1.y += v1 * h1.y; a1.z += v1 * h1.z; a1.w += v1 * h1.w;
    }
    if (i < e) {
        uint2 p0 = __ldg(&ecv[i]);
        float4 h0 = ldg_bf16x4(hsrc + (size_t)p0.x * 32 + lane);
        float v0 = __uint_as_float(p0.y);
        a0.x += v0 * h0.x; a0.y += v0 * h0.y; a0.z += v0 * h0.z; a0.w += v0 * h0.w;
    }
    size_t R = (size_t)(r + row_off);
    float c0 = __ldg(&coe[0]);
    float cw = __ldg(&coe[c_own]);
    float ch = __ldg(&coe[c_hop]);
    float4 xv = __ldg((const float4*)(xbase + R * D) + lane);
    float4 hv = ldg_bf16x4(hown + (size_t)r * 32 + lane);
    float o0 = c0 * xv.x + cw * hv.x + ch * (a0.x + a1.x);
    float o1 = c0 * xv.y + cw * hv.y + ch * (a0.y + a1.y);
    float o2 = c0 * xv.z + cw * hv.z + ch * (a0.z + a1.z);
    float o3 = c0 * xv.w + cw * hv.w + ch * (a0.w + a1.w);

    // out-GEMM: lane holds features 4*lane..4*lane+3
    float p[C_OUT];
    #pragma unroll
    for (int c = 0; c < C_OUT; c++) {
        float4 w = *(const float4*)&sW[c][lane * 4];
        p[c] = o0 * w.x + o1 * w.y + o2 * w.z + o3 * w.w;
    }
    #pragma unroll
    for (int off = 16; off; off >>= 1) {
        #pragma unroll
        for (int c = 0; c < C_OUT; c++)
            p[c] += __shfl_xor_sync(0xffffffffu, p[c], off);
    }
    if (lane < C_OUT)
        out[R * C_OUT + lane] = p[lane] + sb2[lane];
}

// ----------------------------------- launch ---------------------------------
extern "C" void kernel_launch(void* const* d_in, const int* in_sizes, int n_in,
                              void* d_out, int out_size) {
    const float* x0      = (const float*)d_in[0];
    const float* x1      = (const float*)d_in[1];
    const float* vals_ap = (const float*)d_in[2];
    const float* vals_pa = (const float*)d_in[3];
    const int*   rows_ap = (const int*)  d_in[4];
    const int*   cols_ap = (const int*)  d_in[5];
    const int*   rows_pa = (const int*)  d_in[6];
    const int*   cols_pa = (const int*)  d_in[7];
    const float* Wp0     = (const float*)d_in[8];
    const float* Wp1     = (const float*)d_in[9];
    const float* W1      = (const float*)d_in[10];
    const float* b1      = (const float*)d_in[11];
    const float* W2      = (const float*)d_in[12];
    const float* b2      = (const float*)d_in[13];
    const float* coe     = (const float*)d_in[14];
    float* out = (float*)d_out;

    const int E1 = in_sizes[2];
    const int E2 = in_sizes[3];

    float *px, *pres, *pW0c, *pW1c;
    uint2 *pxh, *presh, *phA, *phP, *pecvA, *pecvP;
    int *pcntA, *pcntP, *prpA, *prpP, *poffA, *poffP, *pbA, *pbP;
    cudaGetSymbolAddress((void**)&px,    g_x);
    cudaGetSymbolAddress((void**)&pres,  g_res);
    cudaGetSymbolAddress((void**)&pxh,   g_xh);
    cudaGetSymbolAddress((void**)&presh, g_resh);
    cudaGetSymbolAddress((void**)&phA,   g_hA);
    cudaGetSymbolAddress((void**)&phP,   g_hP);
    cudaGetSymbolAddress((void**)&pW0c,  g_W0c);
    cudaGetSymbolAddress((void**)&pW1c,  g_W1c);
    cudaGetSymbolAddress((void**)&pcntA, g_cntA);
    cudaGetSymbolAddress((void**)&pcntP, g_cntP);
    cudaGetSymbolAddress((void**)&prpA,  g_rpA);
    cudaGetSymbolAddress((void**)&prpP,  g_rpP);
    cudaGetSymbolAddress((void**)&poffA, g_offA);
    cudaGetSymbolAddress((void**)&poffP, g_offP);
    cudaGetSymbolAddress((void**)&pbA,   g_bsumA);
    cudaGetSymbolAddress((void**)&pbP,   g_bsumP);
    cudaGetSymbolAddress((void**)&pecvA, g_ecvA);
    cudaGetSymbolAddress((void**)&pecvP, g_ecvP);

    const int nbA = (N_A + 2047) / 2048;
    const int nbP = (N_P + 2047) / 2048;
    const int gA = (N_A * 32 + 255) / 256;
    const int gP = (N_P * 32 + 255) / 256;

    // 0) weight pre-combine + fused projection/relu/normalize (fp32 + bf16 shadow)
    wcomb_kernel<<<D, D>>>(Wp0, W1, pW0c);
    wcomb_kernel<<<D, D>>>(Wp1, W1, pW1c);
    proj_norm_kernel<<<(N_A + 31) / 32, 256>>>(x0, N_A, pW0c, b1, px, pxh);
    proj_norm_kernel<<<(N_P + 31) / 32, 256>>>(x1, N_P, pW1c, b1,
                                               px + (size_t)N_A * D, pxh + (size_t)N_A * 32);

    // 1) CSR build
    cudaMemsetAsync(pcntA, 0, N_A * sizeof(int));
    cudaMemsetAsync(pcntP, 0, N_P * sizeof(int));
    hist_kernel<<<(E1 + 255) / 256, 256>>>(rows_ap, E1, pcntA, 0);
    hist_kernel<<<(E2 + 255) / 256, 256>>>(rows_pa, E2, pcntP, N_A);
    scan1_kernel<<<nbA, 256>>>(pcntA, N_A, prpA, pbA);
    scan1_kernel<<<nbP, 256>>>(pcntP, N_P, prpP, pbP);
    scan2_kernel<<<1, 256>>>(pbA, nbA);
    scan2_kernel<<<1, 256>>>(pbP, nbP);
    scan3_kernel<<<(N_A + 255) / 256, 256>>>(pbA, N_A, prpA, poffA, pcntA);
    scan3_kernel<<<(N_P + 255) / 256, 256>>>(pbP, N_P, prpP, poffP, pcntP);
    scatter_kernel<<<(E1 + 255) / 256, 256>>>(rows_ap, cols_ap, vals_ap, E1, poffA, pecvA, 0,   N_A);
    scatter_kernel<<<(E2 + 255) / 256, 256>>>(rows_pa, cols_pa, vals_pa, E2, poffP, pecvP, N_A, 0);

    // ---------------- pass 1 (first_order = AP, PA) ----------------
    spmm_csr_kernel<<<gA, 256>>>(prpA, pecvA, pxh + (size_t)N_A * 32, phA, N_A);
    spmm_csr_kernel<<<gP, 256>>>(prpP, pecvP, pxh,                    phP, N_P);
    spmm_csr_fused_kernel<<<gA, 256>>>(prpA, pecvA, phP, px, phA, pres, presh, N_A, 0,   coe, 1, 3);
    spmm_csr_fused_kernel<<<gP, 256>>>(prpP, pecvP, phA, px, phP, pres, presh, N_P, N_A, coe, 2, 4);

    // ---------------- pass 2 (first_order = PA, AP) ----------------
    spmm_csr_kernel<<<gA, 256>>>(prpA, pecvA, presh + (size_t)N_A * 32, phA, N_A);
    spmm_csr_kernel<<<gP, 256>>>(prpP, pecvP, presh,                    phP, N_P);
    spmm_csr_fused_out_kernel<<<gA, 256>>>(prpA, pecvA, phP, pres, phA, out, N_A, 0,   coe, 2, 4, W2, b2);
    spmm_csr_fused_out_kernel<<<gP, 256>>>(prpP, pecvP, phA, pres, phP, out, N_P, N_A, coe, 1, 3, W2, b2);
}

// round 4
// speedup vs baseline: 2.4102x; 1.0305x over previous
#include <cuda_runtime.h>
#include <cuda_bf16.h>
#include <cstddef>
#include <cstdint>

#define N_A   100000
#define N_P   150000
#define N_TOT (N_A + N_P)
#define D     128
#define C_OUT 16
#define EMAX  2000000

// -------------------- device scratch (no allocs allowed) --------------------
__device__ float g_x   [(size_t)N_TOT * D];   // fp32 x after proj (spine)
__device__ float g_res [(size_t)N_TOT * D];   // fp32 res1 (spine)
__device__ uint2 g_xh  [(size_t)N_TOT * 32];  // bf16x4 shadow of x
__device__ uint2 g_resh[(size_t)N_TOT * 32];  // bf16x4 shadow of res1
__device__ uint2 g_hA  [(size_t)N_A  * 32];   // bf16 hop-1 output (A rows)
__device__ uint2 g_hP  [(size_t)N_P  * 32];   // bf16 hop-1 output (P rows)
__device__ float g_W0c [D * D];
__device__ float g_W1c [D * D];
// CSR scratch
__device__ int   g_cntA[N_A],     g_cntP[N_P];
__device__ int   g_rpA [N_A + 1], g_rpP [N_P + 1];
__device__ int   g_offA[N_A],     g_offP[N_P];
__device__ int   g_bsumA[256],    g_bsumP[256];
__device__ uint2 g_ecvA[EMAX],    g_ecvP[EMAX];   // (col_local, val bits)

// ----------------------------- bf16 helpers ---------------------------------
__device__ __forceinline__ float bf_lo(uint32_t u) { return __uint_as_float(u << 16); }
__device__ __forceinline__ float bf_hi(uint32_t u) { return __uint_as_float(u & 0xffff0000u); }

__device__ __forceinline__ float4 ldg_bf16x4(const uint2* p) {
    uint2 r = __ldg(p);
    return make_float4(bf_lo(r.x), bf_hi(r.x), bf_lo(r.y), bf_hi(r.y));
}
__device__ __forceinline__ uint2 pack_bf16x4(float4 v) {
    __nv_bfloat162 a = __floats2bfloat162_rn(v.x, v.y);
    __nv_bfloat162 b = __floats2bfloat162_rn(v.z, v.w);
    uint2 r;
    r.x = *reinterpret_cast<const uint32_t*>(&a);
    r.y = *reinterpret_cast<const uint32_t*>(&b);
    return r;
}
__device__ __forceinline__ uint4 pack_bf16x8(const float* a) {
    __nv_bfloat162 b0 = __floats2bfloat162_rn(a[0], a[1]);
    __nv_bfloat162 b1 = __floats2bfloat162_rn(a[2], a[3]);
    __nv_bfloat162 b2 = __floats2bfloat162_rn(a[4], a[5]);
    __nv_bfloat162 b3 = __floats2bfloat162_rn(a[6], a[7]);
    uint4 r;
    r.x = *reinterpret_cast<const uint32_t*>(&b0);
    r.y = *reinterpret_cast<const uint32_t*>(&b1);
    r.z = *reinterpret_cast<const uint32_t*>(&b2);
    r.w = *reinterpret_cast<const uint32_t*>(&b3);
    return r;
}
__device__ __forceinline__ void accum8(float* a, uint4 h, float v) {
    a[0] += v * bf_lo(h.x); a[1] += v * bf_hi(h.x);
    a[2] += v * bf_lo(h.y); a[3] += v * bf_hi(h.y);
    a[4] += v * bf_lo(h.z); a[5] += v * bf_hi(h.z);
    a[6] += v * bf_lo(h.w); a[7] += v * bf_hi(h.w);
}

// ------------------------- shared gather loop -------------------------------
// Half-warp edge pairing: lanes 0-15 edge i, lanes 16-31 edge i+1; each lane
// loads uint4 = 8 bf16 features (feats lh*8..lh*8+7). After reduction across
// halves, ALL lanes hold the full 8-feature sums for their lh.
__device__ __forceinline__ void gather_row(
    const uint2* __restrict__ ecv, const uint4* __restrict__ src,
    int s, int e, int half, int lh, float* acc /*[8]*/) {
    float acc1[8] = {0, 0, 0, 0, 0, 0, 0, 0};
    int i = s;
    for (; i + 4 <= e; i += 4) {
        uint2 pa = __ldg(&ecv[i + half]);
        uint2 pb = __ldg(&ecv[i + 2 + half]);
        uint4 ha = __ldg(&src[(size_t)pa.x * 16 + lh]);
        uint4 hb = __ldg(&src[(size_t)pb.x * 16 + lh]);
        accum8(acc, ha, __uint_as_float(pa.y));
        accum8(acc1, hb, __uint_as_float(pb.y));
    }
    for (; i < e; i += 2) {
        int idx = i + half;
        uint2 p = __ldg(&ecv[idx < e ? idx : s]);
        float v = (idx < e) ? __uint_as_float(p.y) : 0.f;
        uint4 h = __ldg(&src[(size_t)p.x * 16 + lh]);
        accum8(acc, h, v);
    }
    #pragma unroll
    for (int j = 0; j < 8; j++) {
        acc[j] += acc1[j];
        acc[j] += __shfl_xor_sync(0xffffffffu, acc[j], 16);
    }
}

// redistribute 16-lane x 8-feat layout -> 32-lane x float4 layout
__device__ __forceinline__ float4 redist(const float* acc, int lane) {
    int srcl = lane >> 1;
    bool hi = lane & 1;
    float a0 = __shfl_sync(0xffffffffu, acc[0], srcl);
    float a1 = __shfl_sync(0xffffffffu, acc[1], srcl);
    float a2 = __shfl_sync(0xffffffffu, acc[2], srcl);
    float a3 = __shfl_sync(0xffffffffu, acc[3], srcl);
    float b0 = __shfl_sync(0xffffffffu, acc[4], srcl);
    float b1 = __shfl_sync(0xffffffffu, acc[5], srcl);
    float b2 = __shfl_sync(0xffffffffu, acc[6], srcl);
    float b3 = __shfl_sync(0xffffffffu, acc[7], srcl);
    return make_float4(hi ? b0 : a0, hi ? b1 : a1, hi ? b2 : a2, hi ? b3 : a3);
}

// -------------------- Wc = Wp @ W1 -----------------
__global__ void __launch_bounds__(128) wcomb_kernel(const float* __restrict__ Wp,
                                                    const float* __restrict__ W1,
                                                    float* __restrict__ Wc) {
    __shared__ float srow[D];
    int r = blockIdx.x;
    srow[threadIdx.x] = Wp[r * D + threadIdx.x];
    __syncthreads();
    float acc = 0.f;
    #pragma unroll 8
    for (int k = 0; k < D; k++)
        acc += srow[k] * __ldg(&W1[k * D + threadIdx.x]);
    Wc[r * D + threadIdx.x] = acc;
}

// ------------- fused projection GEMM + bias + relu + row-normalize ----------
// merged A+P launch, 64-row tiles, 8x4 per thread
__global__ void __launch_bounds__(256) proj_norm_kernel(
    const float* __restrict__ x0, const float* __restrict__ x1,
    const float* __restrict__ Wc0, const float* __restrict__ Wc1,
    const float* __restrict__ bias,
    float* __restrict__ xout, uint2* __restrict__ xout_h) {
    __shared__ float sA[64][128];
    __shared__ float sB[32][128];

    const int nblkA = (N_A + 63) / 64;
    const float* xin;
    const float* Wc;
    int row0, nrows, base_out;
    if ((int)blockIdx.x < nblkA) {
        xin = x0; Wc = Wc0; row0 = blockIdx.x * 64; nrows = N_A; base_out = 0;
    } else {
        xin = x1; Wc = Wc1; row0 = (blockIdx.x - nblkA) * 64; nrows = N_P; base_out = N_A;
    }
    const int tid = threadIdx.x;

    // load A tile (64x128) zero-padded
    #pragma unroll
    for (int i = 0; i < 8; i++) {
        int idx = tid + i * 256;      // float4 index 0..2047
        int r   = idx >> 5;
        int k4  = idx & 31;
        float4 v = make_float4(0.f, 0.f, 0.f, 0.f);
        if (row0 + r < nrows)
            v = __ldg((const float4*)(xin + (size_t)(row0 + r) * D) + k4);
        *(float4*)&sA[r][k4 * 4] = v;
    }

    const int tr = tid >> 5;   // warp -> rows tr*8..tr*8+7
    const int tc = tid & 31;   // lane -> cols tc*4..tc*4+3
    float acc[8][4];
    #pragma unroll
    for (int i = 0; i < 8; i++)
        #pragma unroll
        for (int j = 0; j < 4; j++) acc[i][j] = 0.f;

    for (int kc = 0; kc < 4; kc++) {
        __syncthreads();
        #pragma unroll
        for (int i = 0; i < 4; i++) {
            int idx = tid + i * 256;
            int kk  = idx >> 5;
            int c4  = idx & 31;
            *(float4*)&sB[kk][c4 * 4] =
                __ldg((const float4*)(Wc + (size_t)(kc * 32 + kk) * D) + c4);
        }
        __syncthreads();
        #pragma unroll
        for (int kk = 0; kk < 32; kk++) {
            float4 bv = *(float4*)&sB[kk][tc * 4];
            #pragma unroll
            for (int i = 0; i < 8; i++) {
                float a = sA[tr * 8 + i][kc * 32 + kk];
                acc[i][0] += a * bv.x; acc[i][1] += a * bv.y;
                acc[i][2] += a * bv.z; acc[i][3] += a * bv.w;
            }
        }
    }

    float4 bv = __ldg((const float4*)bias + tc);
    float bb[4] = {bv.x, bv.y, bv.z, bv.w};
    #pragma unroll
    for (int i = 0; i < 8; i++)
        #pragma unroll
        for (int j = 0; j < 4; j++) {
            float v = acc[i][j] + bb[j];
            acc[i][j] = v > 0.f ? v : 0.f;
        }

    #pragma unroll
    for (int i = 0; i < 8; i++) {
        float s = acc[i][0] + acc[i][1] + acc[i][2] + acc[i][3];
        float q = acc[i][0]*acc[i][0] + acc[i][1]*acc[i][1]
                + acc[i][2]*acc[i][2] + acc[i][3]*acc[i][3];
        #pragma unroll
        for (int o = 16; o; o >>= 1) {
            s += __shfl_xor_sync(0xffffffffu, s, o);
            q += __shfl_xor_sync(0xffffffffu, q, o);
        }
        float mean = s * (1.f / 128.f);
        float var  = (q - 128.f * mean * mean) * (1.f / 127.f);
        float rstd = (var > 0.f) ? rsqrtf(var) : 0.f;
        int r = row0 + tr * 8 + i;
        if (r < nrows) {
            size_t R = (size_t)(base_out + r);
            float4 o;
            o.x = (acc[i][0] - mean) * rstd;
            o.y = (acc[i][1] - mean) * rstd;
            o.z = (acc[i][2] - mean) * rstd;
            o.w = (acc[i][3] - mean) * rstd;
            *(float4*)(xout + R * D + tc * 4) = o;
            xout_h[R * 32 + tc] = pack_bf16x4(o);
        }
    }
}

// ------------------------------ CSR build (merged) ---------------------------
__global__ void __launch_bounds__(256) hist2_kernel(
    const int* __restrict__ rowsA, int E1, int* __restrict__ cntA,
    const int* __restrict__ rowsP, int E2, int* __restrict__ cntP) {
    int i = blockIdx.x * 256 + threadIdx.x;
    if (i < E1) atomicAdd(&cntA[__ldg(&rowsA[i])], 1);
    if (i < E2) atomicAdd(&cntP[__ldg(&rowsP[i]) - N_A], 1);
}

__global__ void __launch_bounds__(256) scan1_kernel(
    const int* __restrict__ cntA, int nA, int* __restrict__ rpA, int* __restrict__ bsumA, int nbA,
    const int* __restrict__ cntP, int nP, int* __restrict__ rpP, int* __restrict__ bsumP) {
    __shared__ int wsum[8];
    const int* cnt; int n; int* rp; int* bsum; int blk;
    if ((int)blockIdx.x < nbA) { cnt = cntA; n = nA; rp = rpA; bsum = bsumA; blk = blockIdx.x; }
    else                       { cnt = cntP; n = nP; rp = rpP; bsum = bsumP; blk = blockIdx.x - nbA; }
    const int base = blk * 2048;
    const int t = threadIdx.x;
    int v[8]; int s = 0;
    #pragma unroll
    for (int i = 0; i < 8; i++) {
        int idx = base + t * 8 + i;
        int c = (idx < n) ? __ldg(&cnt[idx]) : 0;
        v[i] = s; s += c;
    }
    int lane = t & 31, w = t >> 5;
    int p = s;
    #pragma unroll
    for (int o = 1; o < 32; o <<= 1) {
        int q = __shfl_up_sync(0xffffffffu, p, o);
        if (lane >= o) p += q;
    }
    if (lane == 31) wsum[w] = p;
    __syncthreads();
    if (t < 8) {
        int ws = wsum[t];
        int pp = ws;
        #pragma unroll
        for (int o = 1; o < 8; o <<= 1) {
            int q = __shfl_up_sync(0xffu, pp, o);
            if (t >= o) pp += q;
        }
        wsum[t] = pp - ws;
        if (t == 7) bsum[blk] = pp;
    }
    __syncthreads();
    int texcl = (p - s) + wsum[w];
    #pragma unroll
    for (int i = 0; i < 8; i++) {
        int idx = base + t * 8 + i;
        if (idx < n) rp[idx] = texcl + v[i];
    }
}

__global__ void __launch_bounds__(256) scan2_kernel(
    int* __restrict__ bsumA, int nbA, int* __restrict__ bsumP, int nbP) {
    __shared__ int sh[256];
    int* bsum = blockIdx.x == 0 ? bsumA : bsumP;
    int nb    = blockIdx.x == 0 ? nbA   : nbP;
    int t = threadIdx.x;
    int v = (t < nb) ? bsum[t] : 0;
    sh[t] = v; __syncthreads();
    #pragma unroll
    for (int o = 1; o < 256; o <<= 1) {
        int q = (t >= o) ? sh[t - o] : 0;
        __syncthreads();
        sh[t] += q;
        __syncthreads();
    }
    if (t < nb) bsum[t] = sh[t] - v;
}

__global__ void __launch_bounds__(256) scan3_kernel(
    const int* __restrict__ bsumA, int nA, int* __restrict__ rpA, int* __restrict__ offsA,
    const int* __restrict__ cntA, int ngA,
    const int* __restrict__ bsumP, int nP, int* __restrict__ rpP, int* __restrict__ offsP,
    const int* __restrict__ cntP) {
    const int* bsum; int n; int* rp; int* offs; const int* cnt; int idx;
    if ((int)blockIdx.x < ngA) {
        bsum = bsumA; n = nA; rp = rpA; offs = offsA; cnt = cntA;
        idx = blockIdx.x * 256 + threadIdx.x;
    } else {
        bsum = bsumP; n = nP; rp = rpP; offs = offsP; cnt = cntP;
        idx = (blockIdx.x - ngA) * 256 + threadIdx.x;
    }
    if (idx < n) {
        int v = rp[idx] + __ldg(&bsum[idx >> 11]);
        rp[idx] = v;
        offs[idx] = v;
        if (idx == n - 1) rp[n] = v + __ldg(&cnt[idx]);
    }
}

__global__ void __launch_bounds__(256) scatter2_kernel(
    const int* __restrict__ rowsA, const int* __restrict__ colsA,
    const float* __restrict__ valsA, int E1, int* __restrict__ offsA, uint2* __restrict__ ecvA,
    const int* __restrict__ rowsP, const int* __restrict__ colsP,
    const float* __restrict__ valsP, int E2, int* __restrict__ offsP, uint2* __restrict__ ecvP) {
    int i = blockIdx.x * 256 + threadIdx.x;
    if (i < E1) {
        int r = __ldg(&rowsA[i]);
        int pos = atomicAdd(&offsA[r], 1);
        ecvA[pos] = make_uint2((unsigned)(__ldg(&colsA[i]) - N_A), __float_as_uint(__ldg(&valsA[i])));
    }
    if (i < E2) {
        int r = __ldg(&rowsP[i]) - N_A;
        int pos = atomicAdd(&offsP[r], 1);
        ecvP[pos] = make_uint2((unsigned)__ldg(&colsP[i]), __float_as_uint(__ldg(&valsP[i])));
    }
}

// ----------------------------- CSR SpMM (hop 1) -----------------------------
__global__ void __launch_bounds__(256) spmm_csr_kernel(
    const int* __restrict__ rp, const uint2* __restrict__ ecv,
    const uint4* __restrict__ src, uint4* __restrict__ dst, int nrows) {
    int r = (int)((blockIdx.x * 256u + threadIdx.x) >> 5);
    if (r >= nrows) return;
    int lane = threadIdx.x & 31, half = lane >> 4, lh = lane & 15;
    int s = __ldg(&rp[r]), e = __ldg(&rp[r + 1]);
    float acc[8] = {0, 0, 0, 0, 0, 0, 0, 0};
    gather_row(ecv, src, s, e, half, lh, acc);
    if (half == 0)
        dst[(size_t)r * 16 + lh] = pack_bf16x8(acc);
}

// ------------------- pass-1 hop-2 fused with combine ------------------------
__global__ void __launch_bounds__(256) spmm_csr_fused_kernel(
    const int* __restrict__ rp, const uint2* __restrict__ ecv,
    const uint4* __restrict__ hsrc,
    const float* __restrict__ xbase, const uint2* __restrict__ hown,
    float* __restrict__ resbase, uint2* __restrict__ resh,
    int nrows, int row_off,
    const float* __restrict__ coe, int c_own, int c_hop) {
    int r = (int)((blockIdx.x * 256u + threadIdx.x) >> 5);
    if (r >= nrows) return;
    int lane = threadIdx.x & 31, half = lane >> 4, lh = lane & 15;
    int s = __ldg(&rp[r]), e = __ldg(&rp[r + 1]);
    float acc[8] = {0, 0, 0, 0, 0, 0, 0, 0};
    gather_row(ecv, hsrc, s, e, half, lh, acc);
    float4 w = redist(acc, lane);

    size_t R = (size_t)(r + row_off);
    float c0 = __ldg(&coe[0]);
    float cw = __ldg(&coe[c_own]);
    float ch = __ldg(&coe[c_hop]);
    float4 xv = __ldg((const float4*)(xbase + R * D) + lane);
    float4 hv = ldg_bf16x4(hown + (size_t)r * 32 + lane);
    float4 o;
    o.x = c0 * xv.x + cw * hv.x + ch * w.x;
    o.y = c0 * xv.y + cw * hv.y + ch * w.y;
    o.z = c0 * xv.z + cw * hv.z + ch * w.z;
    o.w = c0 * xv.w + cw * hv.w + ch * w.w;
    *((float4*)(resbase + R * D) + lane) = o;
    resh[R * 32 + lane] = pack_bf16x4(o);
}

// ----------- pass-2 hop-2 fused with combine AND output GEMM ----------------
__global__ void __launch_bounds__(256) spmm_csr_fused_out_kernel(
    const int* __restrict__ rp, const uint2* __restrict__ ecv,
    const uint4* __restrict__ hsrc,
    const float* __restrict__ xbase, const uint2* __restrict__ hown,
    float* __restrict__ out, int nrows, int row_off,
    const float* __restrict__ coe, int c_own, int c_hop,
    const float* __restrict__ W2, const float* __restrict__ b2) {
    __shared__ float sW[C_OUT][D];
    __shared__ float sb2[C_OUT];
    int tid = threadIdx.x;
    for (int i = tid; i < C_OUT * D; i += 256) {
        int c = i >> 7, k = i & 127;
        sW[c][k] = __ldg(&W2[k * C_OUT + c]);
    }
    if (tid < C_OUT) sb2[tid] = __ldg(&b2[tid]);
    __syncthreads();

    int r = (int)((blockIdx.x * 256u + tid) >> 5);
    if (r >= nrows) return;
    int lane = tid & 31, half = lane >> 4, lh = lane & 15;
    int s = __ldg(&rp[r]), e = __ldg(&rp[r + 1]);
    float acc[8] = {0, 0, 0, 0, 0, 0, 0, 0};
    gather_row(ecv, hsrc, s, e, half, lh, acc);
    float4 w = redist(acc, lane);

    size_t R = (size_t)(r + row_off);
    float c0 = __ldg(&coe[0]);
    float cw = __ldg(&coe[c_own]);
    float ch = __ldg(&coe[c_hop]);
    float4 xv = __ldg((const float4*)(xbase + R * D) + lane);
    float4 hv = ldg_bf16x4(hown + (size_t)r * 32 + lane);
    float o0 = c0 * xv.x + cw * hv.x + ch * w.x;
    float o1 = c0 * xv.y + cw * hv.y + ch * w.y;
    float o2 = c0 * xv.z + cw * hv.z + ch * w.z;
    float o3 = c0 * xv.w + cw * hv.w + ch * w.w;

    float p[C_OUT];
    #pragma unroll
    for (int c = 0; c < C_OUT; c++) {
        float4 wv = *(const float4*)&sW[c][lane * 4];
        p[c] = o0 * wv.x + o1 * wv.y + o2 * wv.z + o3 * wv.w;
    }
    #pragma unroll
    for (int off = 16; off; off >>= 1) {
        #pragma unroll
        for (int c = 0; c < C_OUT; c++)
            p[c] += __shfl_xor_sync(0xffffffffu, p[c], off);
    }
    if (lane < C_OUT)
        out[R * C_OUT + lane] = p[lane] + sb2[lane];
}

// ----------------------------------- launch ---------------------------------
extern "C" void kernel_launch(void* const* d_in, const int* in_sizes, int n_in,
                              void* d_out, int out_size) {
    const float* x0      = (const float*)d_in[0];
    const float* x1      = (const float*)d_in[1];
    const float* vals_ap = (const float*)d_in[2];
    const float* vals_pa = (const float*)d_in[3];
    const int*   rows_ap = (const int*)  d_in[4];
    const int*   cols_ap = (const int*)  d_in[5];
    const int*   rows_pa = (const int*)  d_in[6];
    const int*   cols_pa = (const int*)  d_in[7];
    const float* Wp0     = (const float*)d_in[8];
    const float* Wp1     = (const float*)d_in[9];
    const float* W1      = (const float*)d_in[10];
    const float* b1      = (const float*)d_in[11];
    const float* W2      = (const float*)d_in[12];
    const float* b2      = (const float*)d_in[13];
    const float* coe     = (const float*)d_in[14];
    float* out = (float*)d_out;

    const int E1 = in_sizes[2];
    const int E2 = in_sizes[3];

    float *px, *pres, *pW0c, *pW1c;
    uint2 *pxh, *presh, *phA, *phP, *pecvA, *pecvP;
    int *pcntA, *pcntP, *prpA, *prpP, *poffA, *poffP, *pbA, *pbP;
    cudaGetSymbolAddress((void**)&px,    g_x);
    cudaGetSymbolAddress((void**)&pres,  g_res);
    cudaGetSymbolAddress((void**)&pxh,   g_xh);
    cudaGetSymbolAddress((void**)&presh, g_resh);
    cudaGetSymbolAddress((void**)&phA,   g_hA);
    cudaGetSymbolAddress((void**)&phP,   g_hP);
    cudaGetSymbolAddress((void**)&pW0c,  g_W0c);
    cudaGetSymbolAddress((void**)&pW1c,  g_W1c);
    cudaGetSymbolAddress((void**)&pcntA, g_cntA);
    cudaGetSymbolAddress((void**)&pcntP, g_cntP);
    cudaGetSymbolAddress((void**)&prpA,  g_rpA);
    cudaGetSymbolAddress((void**)&prpP,  g_rpP);
    cudaGetSymbolAddress((void**)&poffA, g_offA);
    cudaGetSymbolAddress((void**)&poffP, g_offP);
    cudaGetSymbolAddress((void**)&pbA,   g_bsumA);
    cudaGetSymbolAddress((void**)&pbP,   g_bsumP);
    cudaGetSymbolAddress((void**)&pecvA, g_ecvA);
    cudaGetSymbolAddress((void**)&pecvP, g_ecvP);

    const int nbA = (N_A + 2047) / 2048;
    const int nbP = (N_P + 2047) / 2048;
    const int ngA = (N_A + 255) / 256;
    const int ngP = (N_P + 255) / 256;
    const int gA = (N_A * 32 + 255) / 256;
    const int gP = (N_P * 32 + 255) / 256;
    const int Emax = E1 > E2 ? E1 : E2;

    // 0) weight pre-combine + fused projection/relu/normalize (merged A+P)
    wcomb_kernel<<<D, D>>>(Wp0, W1, pW0c);
    wcomb_kernel<<<D, D>>>(Wp1, W1, pW1c);
    proj_norm_kernel<<<(N_A + 63) / 64 + (N_P + 63) / 64, 256>>>(
        x0, x1, pW0c, pW1c, b1, px, pxh);

    // 1) CSR build (5 launches, both relations per launch)
    cudaMemsetAsync(pcntA, 0, N_A * sizeof(int));
    cudaMemsetAsync(pcntP, 0, N_P * sizeof(int));
    hist2_kernel<<<(Emax + 255) / 256, 256>>>(rows_ap, E1, pcntA, rows_pa, E2, pcntP);
    scan1_kernel<<<nbA + nbP, 256>>>(pcntA, N_A, prpA, pbA, nbA, pcntP, N_P, prpP, pbP);
    scan2_kernel<<<2, 256>>>(pbA, nbA, pbP, nbP);
    scan3_kernel<<<ngA + ngP, 256>>>(pbA, N_A, prpA, poffA, pcntA, ngA,
                                     pbP, N_P, prpP, poffP, pcntP);
    scatter2_kernel<<<(Emax + 255) / 256, 256>>>(
        rows_ap, cols_ap, vals_ap, E1, poffA, pecvA,
        rows_pa, cols_pa, vals_pa, E2, poffP, pecvP);

    // ---------------- pass 1 (first_order = AP, PA) ----------------
    spmm_csr_kernel<<<gA, 256>>>(prpA, pecvA, (const uint4*)(pxh + (size_t)N_A * 32),
                                 (uint4*)phA, N_A);
    spmm_csr_kernel<<<gP, 256>>>(prpP, pecvP, (const uint4*)pxh, (uint4*)phP, N_P);
    spmm_csr_fused_kernel<<<gA, 256>>>(prpA, pecvA, (const uint4*)phP, px, phA,
                                       pres, presh, N_A, 0,   coe, 1, 3);
    spmm_csr_fused_kernel<<<gP, 256>>>(prpP, pecvP, (const uint4*)phA, px, phP,
                                       pres, presh, N_P, N_A, coe, 2, 4);

    // ---------------- pass 2 (first_order = PA, AP) ----------------
    spmm_csr_kernel<<<gA, 256>>>(prpA, pecvA, (const uint4*)(presh + (size_t)N_A * 32),
                                 (uint4*)phA, N_A);
    spmm_csr_kernel<<<gP, 256>>>(prpP, pecvP, (const uint4*)presh, (uint4*)phP, N_P);
    spmm_csr_fused_out_kernel<<<gA, 256>>>(prpA, pecvA, (const uint4*)phP, pres, phA,
                                           out, N_A, 0,   coe, 2, 4, W2, b2);
    spmm_csr_fused_out_kernel<<<gP, 256>>>(prpP, pecvP, (const uint4*)phA, pres, phP,
                                           out, N_P, N_A, coe, 1, 3, W2, b2);
}